// round 2
// baseline (speedup 1.0000x reference)
#include <cuda_runtime.h>
#include <cuda_bf16.h>

#define BB  2048
#define TT  500
#define NIN 64
#define BT  (BB*TT)

// Scratch (allocation-free rule: device global). [t][b] input sums, 4 MB, L2-hot.
__device__ float g_S[TT*BB];

// ---------------------------------------------------------------------------
// K1: per-(b,t) sum over N=64 inputs. 16 lanes/row, 4 timesteps per block so
// each thread has 4 independent float4 loads in flight (MLP=4).
// grid (BB/32, TT/4), block 512 (= 32 b-rows x 16 lanes).
// ---------------------------------------------------------------------------
__global__ void __launch_bounds__(512) reduce_kernel(const float* __restrict__ in) {
    __shared__ float s_sum[4][32];
    int tid   = threadIdx.x;
    int rowid = tid >> 4;          // b within block
    int sub   = tid & 15;
    int b     = blockIdx.x * 32 + rowid;
    int t0    = blockIdx.y * 4;

    float s[4];
#pragma unroll
    for (int k = 0; k < 4; k++) {
        const float4* p = (const float4*)(in + ((size_t)b * TT + t0 + k) * NIN);
        float4 v = p[sub];
        s[k] = (v.x + v.y) + (v.z + v.w);
    }
#pragma unroll
    for (int k = 0; k < 4; k++) {
        s[k] += __shfl_down_sync(0xFFFFFFFFu, s[k], 8);
        s[k] += __shfl_down_sync(0xFFFFFFFFu, s[k], 4);
        s[k] += __shfl_down_sync(0xFFFFFFFFu, s[k], 2);
        s[k] += __shfl_down_sync(0xFFFFFFFFu, s[k], 1);
    }
    if (sub == 0) {
#pragma unroll
        for (int k = 0; k < 4; k++) s_sum[k][rowid] = s[k];
    }
    __syncthreads();
    if (tid < 128)
        g_S[(t0 + (tid >> 5)) * BB + blockIdx.x * 32 + (tid & 31)] = s_sum[tid >> 5][tid & 31];
}

// ---------------------------------------------------------------------------
// K2: sequential scan, one thread = one batch element, BOTH channels inline
// (2 independent dependency chains per thread -> ILP-2 latency hiding).
// Outputs staged 16 timesteps at a time in smem, flushed with coalesced
// stores directly into the final [B,T] / [B,T,4] layout (no scratch pass).
// 64 blocks x 32 threads.
// ---------------------------------------------------------------------------
__device__ __forceinline__ void izh(float& v, float& u, float& z, float I,
                                    float a, float bb, float c, float d) {
    float vn = v + 0.25f * (0.04f * v * v + 5.0f * v + 140.0f - u + I);
    float un = u + (0.25f * a) * (bb * v - u);
    bool sp = (vn >= 30.0f);
    z = sp ? 1.0f : 0.0f;
    v = sp ? c : vn;
    u = sp ? (un + d) : un;
}

// tile planes: 0..3 = z2,z3,z4,z5 (ch0) | 4..7 = vL,vE,vI,vT (ch0)
//              8 = z6, 9 = vM (ch0)     | 10 = z62, 11 = vM2 (ch1)
#define TSTEP 16

__global__ void __launch_bounds__(32, 1) scan_kernel(const float* __restrict__ W,
                                                     float* __restrict__ out) {
    __shared__ float tile[12][32][TSTEP + 1];
    int lane = threadIdx.x;
    int b0   = blockIdx.x * 32;
    int b    = b0 + lane;

    // shared weights
    float w2 = W[2], w3 = W[3], w9 = W[9], w10 = W[10];
    // channel-0 weights
    float w0 = W[0], w1 = W[1], w4 = W[4], w5 = W[5], w6 = W[6], w8 = W[8], w11 = W[11];
    // channel-1 weights
    float w12 = W[12], w13 = W[13], w16 = W[16], w17 = W[17], w18 = W[18], w20 = W[20], w23 = W[23];

    // channel-0 state
    float vL = -70.f, uL = -14.f, zL = 0.f;
    float vE = -64.f, uE = -16.f;
    float vI = -64.f, uI = -16.f;
    float vT = -70.f, uT = -14.f, zT = 0.f;
    float vM = -64.f, uM = -16.f;
    // channel-1 state
    float vL2 = -70.f, uL2 = -14.f, zL2 = 0.f;
    float vE2 = -64.f, uE2 = -16.f;
    float vI2 = -64.f, uI2 = -16.f;
    float vT2 = -70.f, uT2 = -14.f, zT2 = 0.f;
    float vM2 = -64.f, uM2 = -16.f;

    // distance-2 prefetch of the L2-hot drive sums
    float s0 = g_S[b];
    float s1 = g_S[BB + b];

    int tb = 0;  // base t of current smem tile
#pragma unroll 1
    for (int t = 0; t < TT; t++) {
        int tf = t + 2; if (tf > TT - 1) tf = TT - 1;
        float s2 = g_S[tf * BB + b];

        float zp  = s0 * w0;
        float zp2 = s0 * w12;
        float z2, z3, z4, z5, z6, z22, z32, z42, z52, z62;

        // channel 0
        izh(vL, uL, z2, w2 * (zp * w1) + w3 * zL,  0.02f, 0.20f, -65.f, 6.f);
        izh(vE, uE, z3, zp * w4 + z2 * w5,         0.02f, 0.25f, -55.f, 0.05f);
        izh(vI, uI, z4, z3 * w6,                   0.02f, 0.25f, -65.f, 6.f);
        izh(vT, uT, z5, w9 * (z3 * w8) + w10 * zT, 0.02f, 0.20f, -50.f, 2.f);
        izh(vM, uM, z6, z5 * w11,                  0.02f, 0.25f, -65.f, 6.f);
        zL = z2; zT = z5;
        // channel 1
        izh(vL2, uL2, z22, w2 * (zp2 * w13) + w3 * zL2,   0.02f, 0.20f, -65.f, 6.f);
        izh(vE2, uE2, z32, zp2 * w16 + z22 * w17,         0.02f, 0.25f, -55.f, 0.05f);
        izh(vI2, uI2, z42, z32 * w18,                     0.02f, 0.25f, -65.f, 6.f);
        izh(vT2, uT2, z52, w9 * (z32 * w20) + w10 * zT2,  0.02f, 0.20f, -50.f, 2.f);
        izh(vM2, uM2, z62, z52 * w23,                     0.02f, 0.25f, -65.f, 6.f);
        zL2 = z22; zT2 = z52;

        int tl = t - tb;
        tile[0][lane][tl] = z2;   tile[1][lane][tl] = z3;
        tile[2][lane][tl] = z4;   tile[3][lane][tl] = z5;
        tile[4][lane][tl] = vL;   tile[5][lane][tl] = vE;
        tile[6][lane][tl] = vI;   tile[7][lane][tl] = vT;
        tile[8][lane][tl] = z6;   tile[9][lane][tl] = vM;
        tile[10][lane][tl] = z62; tile[11][lane][tl] = vM2;

        if (tl == TSTEP - 1 || t == TT - 1) {
            int cnt = tl + 1;
            __syncwarp();
            int half = lane >> 4;      // 0/1 -> which of 2 b-rows per instruction
            int tt   = lane & 15;      // t within tile
            // scalar output planes 0..3  <- tile planes 8..11
#pragma unroll 1
            for (int r = 0; r < 64; r++) {
                int p  = r >> 4;
                int bb = ((r & 15) << 1) + half;
                if (tt < cnt)
                    out[(size_t)p * BT + (size_t)(b0 + bb) * TT + tb + tt] = tile[8 + p][bb][tt];
            }
            // [B,T,4] groups: planes 0..3 -> out+4BT, planes 4..7 -> out+8BT
#pragma unroll 1
            for (int r = 0; r < 32; r++) {
                int g  = r >> 4;
                int bb = ((r & 15) << 1) + half;
                if (tt < cnt) {
                    float4 v = make_float4(tile[g * 4 + 0][bb][tt], tile[g * 4 + 1][bb][tt],
                                           tile[g * 4 + 2][bb][tt], tile[g * 4 + 3][bb][tt]);
                    ((float4*)(out + (size_t)(4 + 4 * g) * BT))[(size_t)(b0 + bb) * TT + tb + tt] = v;
                }
            }
            __syncwarp();
            tb = t + 1;
        }

        s0 = s1; s1 = s2;
    }
}

// ---------------------------------------------------------------------------
extern "C" void kernel_launch(void* const* d_in, const int* in_sizes, int n_in,
                              void* d_out, int out_size) {
    const float* in = (const float*)d_in[0];   // [B, T, 64] float32
    const float* w  = (const float*)d_in[1];   // [24] float32
    float* out = (float*)d_out;

    reduce_kernel<<<dim3(BB / 32, TT / 4), 512>>>(in);
    scan_kernel<<<BB / 32, 32>>>(w, out);
}